// round 2
// baseline (speedup 1.0000x reference)
#include <cuda_runtime.h>
#include <cuda_bf16.h>
#include <math.h>

// Problem constants
#define Bc 32
#define Nc 64
#define Fc 1280
#define Hc 512
#define Ec 512
#define Vc 10000
#define Tc 80
#define SOSc 1
#define EFc (Ec + Fc)      // 1792
#define G4 (4 * Hc)        // 2048

// ---------------- device scratch (no allocation allowed) ----------------
__device__ float g_h[2][Bc * Hc];
__device__ float g_c[2][Bc * Hc];
__device__ float g_x[Bc * Ec];
__device__ float g_hq[Bc * Hc];
__device__ float g_glin[Bc * Fc];
__device__ float g_ctx[Bc * Fc];
__device__ float g_encproj[Bc * Nc * Hc];
__device__ float g_mean[Bc * Fc];
__device__ float g_gpart[4][Bc][G4];

// output offsets (flattened pytree: decoder_outputs, h, c, attentions)
#define HOFF ((size_t)Bc * Tc * Vc)          // 25,600,000
#define COFF (HOFF + (size_t)Bc * Hc)
#define AOFF (COFF + (size_t)Bc * Hc)        // 25,632,768

__device__ __forceinline__ float sigf(float x) { return 1.0f / (1.0f + expf(-x)); }

// ---------------- init kernels ----------------
__global__ void k_mean(const float* __restrict__ feat) {
    int idx = blockIdx.x * blockDim.x + threadIdx.x;
    if (idx >= Bc * Fc) return;
    int b = idx / Fc, f = idx % Fc;
    float s = 0.f;
    const float* p = feat + (size_t)b * Nc * Fc + f;
    for (int n = 0; n < Nc; n++) s += p[(size_t)n * Fc];
    g_mean[idx] = s * (1.0f / 64.0f);
}

__global__ void k_h0c0(const float* __restrict__ Wh, const float* __restrict__ bh,
                       const float* __restrict__ Wc, const float* __restrict__ bc) {
    int idx = blockIdx.x * blockDim.x + threadIdx.x;
    if (idx >= 2 * Bc * Hc) return;
    int half = idx / (Bc * Hc);
    int r = idx % (Bc * Hc);
    int b = r / Hc, j = r % Hc;
    const float* W = half ? Wc : Wh;
    float acc = half ? bc[j] : bh[j];
    const float* m = g_mean + b * Fc;
    for (int k = 0; k < Fc; k++) acc += m[k] * W[(size_t)k * Hc + j];
    if (half) g_c[0][r] = acc; else g_h[0][r] = acc;
}

// enc_proj = feat @ W2 + b2   [2048 x 1280] @ [1280 x 512]
__global__ void k_encproj(const float* __restrict__ feat, const float* __restrict__ W2,
                          const float* __restrict__ b2) {
    int tid = threadIdx.x;
    int rowbase = blockIdx.x * 64;    // rows over B*N = 2048
    int colbase = blockIdx.y * 64;    // cols over H = 512
    int col = colbase + (tid & 63);
    int rgrp = tid >> 6;              // 0..3, 16 rows each
    float acc[16];
#pragma unroll
    for (int i = 0; i < 16; i++) acc[i] = 0.f;
    __shared__ float As[64][32];
    __shared__ float Ws[32][64];
    for (int kc = 0; kc < Fc; kc += 32) {
        for (int e = tid; e < 64 * 32; e += 256) {
            int r = e >> 5, kk = e & 31;
            As[r][kk] = feat[(size_t)(rowbase + r) * Fc + kc + kk];
        }
        for (int e = tid; e < 32 * 64; e += 256) {
            int kk = e >> 6, c = e & 63;
            Ws[kk][c] = W2[(size_t)(kc + kk) * Hc + colbase + c];
        }
        __syncthreads();
        for (int kk = 0; kk < 32; kk++) {
            float w = Ws[kk][tid & 63];
#pragma unroll
            for (int i = 0; i < 16; i++) acc[i] += As[rgrp * 16 + i][kk] * w;
        }
        __syncthreads();
    }
    float bb = b2[col];
#pragma unroll
    for (int i = 0; i < 16; i++)
        g_encproj[(size_t)(rowbase + rgrp * 16 + i) * Hc + col] = acc[i] + bb;
}

__global__ void k_x0(const float* __restrict__ emb) {
    int idx = blockIdx.x * blockDim.x + threadIdx.x;
    if (idx >= Bc * Ec) return;
    int e = idx % Ec;
    g_x[idx] = emb[(size_t)SOSc * Ec + e];
}

// ---------------- per-step kernels ----------------
// hq = h @ W1 + b1 (512 cols) ; glin = h @ Wg + bg (1280 cols). 28 blocks.
__global__ void k_hq_glin(const float* __restrict__ W1, const float* __restrict__ b1,
                          const float* __restrict__ Wg, const float* __restrict__ bg, int rp) {
    int tid = threadIdx.x;
    int colg = blockIdx.x * 64 + (tid & 63);
    int bgrp = tid >> 6;
    const float* Wcol;
    float bias;
    float* dst;
    int dstLd, ldw;
    if (colg < Hc) { Wcol = W1 + colg; bias = b1[colg]; dst = g_hq + colg; dstLd = Hc; ldw = Hc; }
    else { int c = colg - Hc; Wcol = Wg + c; bias = bg[c]; dst = g_glin + c; dstLd = Fc; ldw = Fc; }
    float acc[8];
#pragma unroll
    for (int i = 0; i < 8; i++) acc[i] = 0.f;
    __shared__ float hs[32][64];
    const float* hsrc = g_h[rp];
    for (int kc = 0; kc < Hc; kc += 64) {
        for (int e = tid; e < 32 * 64; e += 256) {
            int bb = e >> 6, kk = e & 63;
            hs[bb][kk] = hsrc[bb * Hc + kc + kk];
        }
        __syncthreads();
        for (int kk = 0; kk < 64; kk++) {
            float w = Wcol[(size_t)(kc + kk) * ldw];
#pragma unroll
            for (int i = 0; i < 8; i++) acc[i] += hs[bgrp * 8 + i][kk] * w;
        }
        __syncthreads();
    }
#pragma unroll
    for (int i = 0; i < 8; i++) dst[(size_t)(bgrp * 8 + i) * dstLd] = acc[i] + bias;
}

// attention: scores -> softmax -> context * sigmoid(glin). One block per batch row.
__global__ void k_attn(const float* __restrict__ feat, const float* __restrict__ Va,
                       const float* __restrict__ bVa, float* __restrict__ dout, int t) {
    int b = blockIdx.x;
    int tid = threadIdx.x;
    __shared__ float sHq[Hc];
    __shared__ float sS[Nc];
    __shared__ float sMax, sInv;
    for (int k = tid; k < Hc; k += 256) sHq[k] = g_hq[b * Hc + k];
    __syncthreads();
    int warp = tid >> 5, lane = tid & 31;
    for (int n = warp; n < Nc; n += 8) {
        const float* ep = g_encproj + (size_t)(b * Nc + n) * Hc;
        float acc = 0.f;
        for (int k = lane; k < Hc; k += 32) {
            float v = sHq[k] + ep[k];
            v = fmaxf(v, 0.f);
            acc += v * Va[k];
        }
#pragma unroll
        for (int o = 16; o; o >>= 1) acc += __shfl_down_sync(0xffffffffu, acc, o);
        if (lane == 0) sS[n] = acc + bVa[0];
    }
    __syncthreads();
    if (tid == 0) {
        float m = sS[0];
        for (int n = 1; n < Nc; n++) m = fmaxf(m, sS[n]);
        sMax = m;
    }
    __syncthreads();
    if (tid < Nc) sS[tid] = expf(sS[tid] - sMax);
    __syncthreads();
    if (tid == 0) {
        float s = 0.f;
        for (int n = 0; n < Nc; n++) s += sS[n];
        sInv = 1.0f / s;
    }
    __syncthreads();
    if (tid < Nc) {
        sS[tid] *= sInv;
        dout[AOFF + (size_t)b * Tc * Nc + (size_t)t * Nc + tid] = sS[tid];
    }
    __syncthreads();
    for (int f = tid; f < Fc; f += 256) {
        float acc = 0.f;
        const float* fb = feat + (size_t)b * Nc * Fc + f;
#pragma unroll 4
        for (int n = 0; n < Nc; n++) acc += fb[(size_t)n * Fc] * sS[n];
        float gl = g_glin[b * Fc + f];
        g_ctx[b * Fc + f] = acc * sigf(gl);
    }
}

// gates partial GEMM: [32 x 2304] @ [2304 x 2048] split over grid (32 coltiles, 4 ksplits)
__global__ void k_gates(const float* __restrict__ Wx, const float* __restrict__ Whh, int rp) {
    const int KS = 576;
    int tid = threadIdx.x;
    int col = blockIdx.x * 64 + (tid & 63);
    int bgrp = tid >> 6;
    int kbase = blockIdx.y * KS;
    float acc[8];
#pragma unroll
    for (int i = 0; i < 8; i++) acc[i] = 0.f;
    __shared__ float xs[32][64];
    const float* hsrc = g_h[rp];
    for (int kc = 0; kc < KS; kc += 64) {
        for (int e = tid; e < 32 * 64; e += 256) {
            int bb = e >> 6, kk = e & 63;
            int kg = kbase + kc + kk;
            float v;
            if (kg < Ec) v = g_x[bb * Ec + kg];
            else if (kg < EFc) v = g_ctx[bb * Fc + kg - Ec];
            else v = hsrc[bb * Hc + kg - EFc];
            xs[bb][kk] = v;
        }
        __syncthreads();
        for (int kk = 0; kk < 64; kk++) {
            int kg = kbase + kc + kk;
            float w = (kg < EFc) ? Wx[(size_t)kg * G4 + col]
                                 : Whh[(size_t)(kg - EFc) * G4 + col];
#pragma unroll
            for (int i = 0; i < 8; i++) acc[i] += xs[bgrp * 8 + i][kk] * w;
        }
        __syncthreads();
    }
#pragma unroll
    for (int i = 0; i < 8; i++) g_gpart[blockIdx.y][bgrp * 8 + i][col] = acc[i];
}

__global__ void k_lstm(const float* __restrict__ blstm, int rp) {
    int idx = blockIdx.x * blockDim.x + threadIdx.x;
    if (idx >= Bc * Hc) return;
    int b = idx / Hc, j = idx % Hc;
    float gi = blstm[j], gf = blstm[j + Hc], gg = blstm[j + 2 * Hc], go = blstm[j + 3 * Hc];
#pragma unroll
    for (int s = 0; s < 4; s++) {
        gi += g_gpart[s][b][j];
        gf += g_gpart[s][b][j + Hc];
        gg += g_gpart[s][b][j + 2 * Hc];
        go += g_gpart[s][b][j + 3 * Hc];
    }
    float iv = sigf(gi), fv = sigf(gf), gv = tanhf(gg), ov = sigf(go);
    float c2 = fv * g_c[rp][idx] + iv * gv;
    float h2 = ov * tanhf(c2);
    g_c[1 - rp][idx] = c2;
    g_h[1 - rp][idx] = h2;
}

// logits = h2 @ Wout + bout, written straight to d_out. 157 blocks x 64 cols.
__global__ void k_logits(const float* __restrict__ Wout, const float* __restrict__ bout,
                         float* __restrict__ dout, int t, int wp) {
    int tid = threadIdx.x;
    int col = blockIdx.x * 64 + (tid & 63);
    int colc = (col < Vc) ? col : (Vc - 1);
    int bgrp = tid >> 6;
    float acc[8];
#pragma unroll
    for (int i = 0; i < 8; i++) acc[i] = 0.f;
    __shared__ float hs[32][64];
    const float* hsrc = g_h[wp];
    for (int kc = 0; kc < Hc; kc += 64) {
        for (int e = tid; e < 32 * 64; e += 256) {
            int bb = e >> 6, kk = e & 63;
            hs[bb][kk] = hsrc[bb * Hc + kc + kk];
        }
        __syncthreads();
        for (int kk = 0; kk < 64; kk++) {
            float w = Wout[(size_t)(kc + kk) * Vc + colc];
#pragma unroll
            for (int i = 0; i < 8; i++) acc[i] += hs[bgrp * 8 + i][kk] * w;
        }
        __syncthreads();
    }
    if (col < Vc) {
        float bo = bout[col];
#pragma unroll
        for (int i = 0; i < 8; i++)
            dout[(size_t)(bgrp * 8 + i) * Tc * Vc + (size_t)t * Vc + col] = acc[i] + bo;
    }
}

// greedy argmax over the logits row in d_out (L2-resident), then gather emb row.
__global__ void k_argmax(const float* __restrict__ dout, const float* __restrict__ emb, int t) {
    int b = blockIdx.x;
    int tid = threadIdx.x;
    const float* row = dout + (size_t)b * Tc * Vc + (size_t)t * Vc;
    float bv = -3.4e38f;
    int bi = Vc;
    for (int v = tid; v < Vc; v += 256) {
        float x = row[v];
        if (x > bv) { bv = x; bi = v; }   // strictly greater keeps lowest index per-thread
    }
    __shared__ float sv[256];
    __shared__ int si[256];
    sv[tid] = bv; si[tid] = bi;
    __syncthreads();
    for (int o = 128; o; o >>= 1) {
        if (tid < o) {
            if (sv[tid + o] > sv[tid] || (sv[tid + o] == sv[tid] && si[tid + o] < si[tid])) {
                sv[tid] = sv[tid + o];
                si[tid] = si[tid + o];
            }
        }
        __syncthreads();
    }
    int best = si[0];
    for (int e = tid; e < Ec; e += 256) g_x[b * Ec + e] = emb[(size_t)best * Ec + e];
}

__global__ void k_final(float* __restrict__ dout, int fp) {
    int idx = blockIdx.x * blockDim.x + threadIdx.x;
    if (idx >= 2 * Bc * Hc) return;
    if (idx < Bc * Hc) dout[HOFF + idx] = g_h[fp][idx];
    else dout[COFF + (idx - Bc * Hc)] = g_c[fp][idx - Bc * Hc];
}

// ---------------- launcher ----------------
extern "C" void kernel_launch(void* const* d_in, const int* in_sizes, int n_in,
                              void* d_out, int out_size) {
    // metadata order: feature_outputs, caption, [max_caption scalar?], emb, W1, b1, W2, b2,
    // Va, bVa, Wh, bh, Wc, bc, Wg, bg, Wx, Whh, blstm, Wout, bout
    int off = (n_in > 2 && in_sizes[2] == 1) ? 1 : 0;
    const float* feat  = (const float*)d_in[0];
    const float* emb   = (const float*)d_in[2 + off];
    const float* W1    = (const float*)d_in[3 + off];
    const float* b1    = (const float*)d_in[4 + off];
    const float* W2    = (const float*)d_in[5 + off];
    const float* b2    = (const float*)d_in[6 + off];
    const float* Va    = (const float*)d_in[7 + off];
    const float* bVa   = (const float*)d_in[8 + off];
    const float* Wh    = (const float*)d_in[9 + off];
    const float* bh    = (const float*)d_in[10 + off];
    const float* Wc    = (const float*)d_in[11 + off];
    const float* bc    = (const float*)d_in[12 + off];
    const float* Wg    = (const float*)d_in[13 + off];
    const float* bg    = (const float*)d_in[14 + off];
    const float* Wx    = (const float*)d_in[15 + off];
    const float* Whh   = (const float*)d_in[16 + off];
    const float* blstm = (const float*)d_in[17 + off];
    const float* Wout  = (const float*)d_in[18 + off];
    const float* bout  = (const float*)d_in[19 + off];
    float* out = (float*)d_out;

    k_mean<<<(Bc * Fc + 255) / 256, 256>>>(feat);
    k_h0c0<<<(2 * Bc * Hc + 255) / 256, 256>>>(Wh, bh, Wc, bc);
    k_encproj<<<dim3(32, 8), 256>>>(feat, W2, b2);
    k_x0<<<(Bc * Ec + 255) / 256, 256>>>(emb);

    for (int t = 0; t < Tc; t++) {
        int rp = t & 1, wp = 1 - rp;
        k_hq_glin<<<28, 256>>>(W1, b1, Wg, bg, rp);
        k_attn<<<Bc, 256>>>(feat, Va, bVa, out, t);
        k_gates<<<dim3(32, 4), 256>>>(Wx, Whh, rp);
        k_lstm<<<(Bc * Hc + 255) / 256, 256>>>(blstm, rp);
        k_logits<<<157, 256>>>(Wout, bout, out, t, wp);
        k_argmax<<<Bc, 256>>>(out, emb, t);
    }
    k_final<<<(2 * Bc * Hc + 255) / 256, 256>>>(out, Tc & 1);
}

// round 3
// speedup vs baseline: 1.0044x; 1.0044x over previous
#include <cuda_runtime.h>
#include <cuda_bf16.h>
#include <math.h>

// Problem constants
#define Bc 32
#define Nc 64
#define Fc 1280
#define Hc 512
#define Ec 512
#define Vc 10000
#define Tc 80
#define SOSc 1
#define EFc (Ec + Fc)      // 1792
#define G4 (4 * Hc)        // 2048

// ---------------- device scratch (no allocation allowed) ----------------
__device__ float g_h[2][Bc * Hc];
__device__ float g_c[2][Bc * Hc];
__device__ float g_x[Bc * Ec];
__device__ float g_hq[Bc * Hc];
__device__ float g_glin[Bc * Fc];
__device__ float g_ctx[Bc * Fc];
__device__ float g_encproj[Bc * Nc * Hc];
__device__ float g_mean[Bc * Fc];
__device__ float g_gpart[4][Bc][G4];

// output offsets (flattened pytree: decoder_outputs, h, c, attentions)
#define HOFF ((size_t)Bc * Tc * Vc)          // 25,600,000
#define COFF (HOFF + (size_t)Bc * Hc)
#define AOFF (COFF + (size_t)Bc * Hc)        // 25,632,768

__device__ __forceinline__ float sigf(float x) { return 1.0f / (1.0f + expf(-x)); }

// ---------------- init kernels ----------------
__global__ void k_mean(const float* __restrict__ feat) {
    int idx = blockIdx.x * blockDim.x + threadIdx.x;
    if (idx >= Bc * Fc) return;
    int b = idx / Fc, f = idx % Fc;
    float s = 0.f;
    const float* p = feat + (size_t)b * Nc * Fc + f;
    for (int n = 0; n < Nc; n++) s += p[(size_t)n * Fc];
    g_mean[idx] = s * (1.0f / 64.0f);
}

__global__ void k_h0c0(const float* __restrict__ Wh, const float* __restrict__ bh,
                       const float* __restrict__ Wc, const float* __restrict__ bc) {
    int idx = blockIdx.x * blockDim.x + threadIdx.x;
    if (idx >= 2 * Bc * Hc) return;
    int half = idx / (Bc * Hc);
    int r = idx % (Bc * Hc);
    int b = r / Hc, j = r % Hc;
    const float* W = half ? Wc : Wh;
    float acc = half ? bc[j] : bh[j];
    const float* m = g_mean + b * Fc;
    for (int k = 0; k < Fc; k++) acc += m[k] * W[(size_t)k * Hc + j];
    if (half) g_c[0][r] = acc; else g_h[0][r] = acc;
}

// enc_proj = feat @ W2 + b2   [2048 x 1280] @ [1280 x 512]
__global__ void k_encproj(const float* __restrict__ feat, const float* __restrict__ W2,
                          const float* __restrict__ b2) {
    int tid = threadIdx.x;
    int rowbase = blockIdx.x * 64;    // rows over B*N = 2048
    int colbase = blockIdx.y * 64;    // cols over H = 512
    int col = colbase + (tid & 63);
    int rgrp = tid >> 6;              // 0..3, 16 rows each
    float acc[16];
#pragma unroll
    for (int i = 0; i < 16; i++) acc[i] = 0.f;
    __shared__ float As[64][32];
    __shared__ float Ws[32][64];
    for (int kc = 0; kc < Fc; kc += 32) {
        for (int e = tid; e < 64 * 32; e += 256) {
            int r = e >> 5, kk = e & 31;
            As[r][kk] = feat[(size_t)(rowbase + r) * Fc + kc + kk];
        }
        for (int e = tid; e < 32 * 64; e += 256) {
            int kk = e >> 6, c = e & 63;
            Ws[kk][c] = W2[(size_t)(kc + kk) * Hc + colbase + c];
        }
        __syncthreads();
        for (int kk = 0; kk < 32; kk++) {
            float w = Ws[kk][tid & 63];
#pragma unroll
            for (int i = 0; i < 16; i++) acc[i] += As[rgrp * 16 + i][kk] * w;
        }
        __syncthreads();
    }
    float bb = b2[col];
#pragma unroll
    for (int i = 0; i < 16; i++)
        g_encproj[(size_t)(rowbase + rgrp * 16 + i) * Hc + col] = acc[i] + bb;
}

__global__ void k_x0(const float* __restrict__ emb) {
    int idx = blockIdx.x * blockDim.x + threadIdx.x;
    if (idx >= Bc * Ec) return;
    int e = idx % Ec;
    g_x[idx] = emb[(size_t)SOSc * Ec + e];
}

// ---------------- per-step kernels ----------------
// hq = h @ W1 + b1 (512 cols) ; glin = h @ Wg + bg (1280 cols). 28 blocks.
__global__ void k_hq_glin(const float* __restrict__ W1, const float* __restrict__ b1,
                          const float* __restrict__ Wg, const float* __restrict__ bg, int rp) {
    int tid = threadIdx.x;
    int colg = blockIdx.x * 64 + (tid & 63);
    int bgrp = tid >> 6;
    const float* Wcol;
    float bias;
    float* dst;
    int dstLd, ldw;
    if (colg < Hc) { Wcol = W1 + colg; bias = b1[colg]; dst = g_hq + colg; dstLd = Hc; ldw = Hc; }
    else { int c = colg - Hc; Wcol = Wg + c; bias = bg[c]; dst = g_glin + c; dstLd = Fc; ldw = Fc; }
    float acc[8];
#pragma unroll
    for (int i = 0; i < 8; i++) acc[i] = 0.f;
    __shared__ float hs[32][64];
    const float* hsrc = g_h[rp];
    for (int kc = 0; kc < Hc; kc += 64) {
        for (int e = tid; e < 32 * 64; e += 256) {
            int bb = e >> 6, kk = e & 63;
            hs[bb][kk] = hsrc[bb * Hc + kc + kk];
        }
        __syncthreads();
        for (int kk = 0; kk < 64; kk++) {
            float w = Wcol[(size_t)(kc + kk) * ldw];
#pragma unroll
            for (int i = 0; i < 8; i++) acc[i] += hs[bgrp * 8 + i][kk] * w;
        }
        __syncthreads();
    }
#pragma unroll
    for (int i = 0; i < 8; i++) dst[(size_t)(bgrp * 8 + i) * dstLd] = acc[i] + bias;
}

// attention: scores -> softmax -> context * sigmoid(glin). One block per batch row.
__global__ void k_attn(const float* __restrict__ feat, const float* __restrict__ Va,
                       const float* __restrict__ bVa, float* __restrict__ dout, int t) {
    int b = blockIdx.x;
    int tid = threadIdx.x;
    __shared__ float sHq[Hc];
    __shared__ float sS[Nc];
    __shared__ float sMax, sInv;
    for (int k = tid; k < Hc; k += 256) sHq[k] = g_hq[b * Hc + k];
    __syncthreads();
    int warp = tid >> 5, lane = tid & 31;
    for (int n = warp; n < Nc; n += 8) {
        const float* ep = g_encproj + (size_t)(b * Nc + n) * Hc;
        float acc = 0.f;
        for (int k = lane; k < Hc; k += 32) {
            float v = sHq[k] + ep[k];
            v = fmaxf(v, 0.f);
            acc += v * Va[k];
        }
#pragma unroll
        for (int o = 16; o; o >>= 1) acc += __shfl_down_sync(0xffffffffu, acc, o);
        if (lane == 0) sS[n] = acc + bVa[0];
    }
    __syncthreads();
    if (tid == 0) {
        float m = sS[0];
        for (int n = 1; n < Nc; n++) m = fmaxf(m, sS[n]);
        sMax = m;
    }
    __syncthreads();
    if (tid < Nc) sS[tid] = expf(sS[tid] - sMax);
    __syncthreads();
    if (tid == 0) {
        float s = 0.f;
        for (int n = 0; n < Nc; n++) s += sS[n];
        sInv = 1.0f / s;
    }
    __syncthreads();
    if (tid < Nc) {
        sS[tid] *= sInv;
        dout[AOFF + (size_t)b * Tc * Nc + (size_t)t * Nc + tid] = sS[tid];
    }
    __syncthreads();
    for (int f = tid; f < Fc; f += 256) {
        float acc = 0.f;
        const float* fb = feat + (size_t)b * Nc * Fc + f;
#pragma unroll 4
        for (int n = 0; n < Nc; n++) acc += fb[(size_t)n * Fc] * sS[n];
        float gl = g_glin[b * Fc + f];
        g_ctx[b * Fc + f] = acc * sigf(gl);
    }
}

// gates partial GEMM: [32 x 2304] @ [2304 x 2048] split over grid (32 coltiles, 4 ksplits)
__global__ void k_gates(const float* __restrict__ Wx, const float* __restrict__ Whh, int rp) {
    const int KS = 576;
    int tid = threadIdx.x;
    int col = blockIdx.x * 64 + (tid & 63);
    int bgrp = tid >> 6;
    int kbase = blockIdx.y * KS;
    float acc[8];
#pragma unroll
    for (int i = 0; i < 8; i++) acc[i] = 0.f;
    __shared__ float xs[32][64];
    const float* hsrc = g_h[rp];
    for (int kc = 0; kc < KS; kc += 64) {
        for (int e = tid; e < 32 * 64; e += 256) {
            int bb = e >> 6, kk = e & 63;
            int kg = kbase + kc + kk;
            float v;
            if (kg < Ec) v = g_x[bb * Ec + kg];
            else if (kg < EFc) v = g_ctx[bb * Fc + kg - Ec];
            else v = hsrc[bb * Hc + kg - EFc];
            xs[bb][kk] = v;
        }
        __syncthreads();
        for (int kk = 0; kk < 64; kk++) {
            int kg = kbase + kc + kk;
            float w = (kg < EFc) ? Wx[(size_t)kg * G4 + col]
                                 : Whh[(size_t)(kg - EFc) * G4 + col];
#pragma unroll
            for (int i = 0; i < 8; i++) acc[i] += xs[bgrp * 8 + i][kk] * w;
        }
        __syncthreads();
    }
#pragma unroll
    for (int i = 0; i < 8; i++) g_gpart[blockIdx.y][bgrp * 8 + i][col] = acc[i];
}

__global__ void k_lstm(const float* __restrict__ blstm, int rp) {
    int idx = blockIdx.x * blockDim.x + threadIdx.x;
    if (idx >= Bc * Hc) return;
    int b = idx / Hc, j = idx % Hc;
    float gi = blstm[j], gf = blstm[j + Hc], gg = blstm[j + 2 * Hc], go = blstm[j + 3 * Hc];
#pragma unroll
    for (int s = 0; s < 4; s++) {
        gi += g_gpart[s][b][j];
        gf += g_gpart[s][b][j + Hc];
        gg += g_gpart[s][b][j + 2 * Hc];
        go += g_gpart[s][b][j + 3 * Hc];
    }
    float iv = sigf(gi), fv = sigf(gf), gv = tanhf(gg), ov = sigf(go);
    float c2 = fv * g_c[rp][idx] + iv * gv;
    float h2 = ov * tanhf(c2);
    g_c[1 - rp][idx] = c2;
    g_h[1 - rp][idx] = h2;
}

// logits = h2 @ Wout + bout, written straight to d_out. 157 blocks x 64 cols.
__global__ void k_logits(const float* __restrict__ Wout, const float* __restrict__ bout,
                         float* __restrict__ dout, int t, int wp) {
    int tid = threadIdx.x;
    int col = blockIdx.x * 64 + (tid & 63);
    int colc = (col < Vc) ? col : (Vc - 1);
    int bgrp = tid >> 6;
    float acc[8];
#pragma unroll
    for (int i = 0; i < 8; i++) acc[i] = 0.f;
    __shared__ float hs[32][64];
    const float* hsrc = g_h[wp];
    for (int kc = 0; kc < Hc; kc += 64) {
        for (int e = tid; e < 32 * 64; e += 256) {
            int bb = e >> 6, kk = e & 63;
            hs[bb][kk] = hsrc[bb * Hc + kc + kk];
        }
        __syncthreads();
        for (int kk = 0; kk < 64; kk++) {
            float w = Wout[(size_t)(kc + kk) * Vc + colc];
#pragma unroll
            for (int i = 0; i < 8; i++) acc[i] += hs[bgrp * 8 + i][kk] * w;
        }
        __syncthreads();
    }
    if (col < Vc) {
        float bo = bout[col];
#pragma unroll
        for (int i = 0; i < 8; i++)
            dout[(size_t)(bgrp * 8 + i) * Tc * Vc + (size_t)t * Vc + col] = acc[i] + bo;
    }
}

// greedy argmax over the logits row in d_out (L2-resident), then gather emb row.
__global__ void k_argmax(const float* __restrict__ dout, const float* __restrict__ emb, int t) {
    int b = blockIdx.x;
    int tid = threadIdx.x;
    const float* row = dout + (size_t)b * Tc * Vc + (size_t)t * Vc;
    float bv = -3.4e38f;
    int bi = Vc;
    for (int v = tid; v < Vc; v += 256) {
        float x = row[v];
        if (x > bv) { bv = x; bi = v; }   // strictly greater keeps lowest index per-thread
    }
    __shared__ float sv[256];
    __shared__ int si[256];
    sv[tid] = bv; si[tid] = bi;
    __syncthreads();
    for (int o = 128; o; o >>= 1) {
        if (tid < o) {
            if (sv[tid + o] > sv[tid] || (sv[tid + o] == sv[tid] && si[tid + o] < si[tid])) {
                sv[tid] = sv[tid + o];
                si[tid] = si[tid + o];
            }
        }
        __syncthreads();
    }
    int best = si[0];
    for (int e = tid; e < Ec; e += 256) g_x[b * Ec + e] = emb[(size_t)best * Ec + e];
}

__global__ void k_final(float* __restrict__ dout, int fp) {
    int idx = blockIdx.x * blockDim.x + threadIdx.x;
    if (idx >= 2 * Bc * Hc) return;
    if (idx < Bc * Hc) dout[HOFF + idx] = g_h[fp][idx];
    else dout[COFF + (idx - Bc * Hc)] = g_c[fp][idx - Bc * Hc];
}

// ---------------- launcher ----------------
extern "C" void kernel_launch(void* const* d_in, const int* in_sizes, int n_in,
                              void* d_out, int out_size) {
    // metadata order: feature_outputs, caption, [max_caption scalar?], emb, W1, b1, W2, b2,
    // Va, bVa, Wh, bh, Wc, bc, Wg, bg, Wx, Whh, blstm, Wout, bout
    int off = (n_in > 2 && in_sizes[2] == 1) ? 1 : 0;
    const float* feat  = (const float*)d_in[0];
    const float* emb   = (const float*)d_in[2 + off];
    const float* W1    = (const float*)d_in[3 + off];
    const float* b1    = (const float*)d_in[4 + off];
    const float* W2    = (const float*)d_in[5 + off];
    const float* b2    = (const float*)d_in[6 + off];
    const float* Va    = (const float*)d_in[7 + off];
    const float* bVa   = (const float*)d_in[8 + off];
    const float* Wh    = (const float*)d_in[9 + off];
    const float* bh    = (const float*)d_in[10 + off];
    const float* Wc    = (const float*)d_in[11 + off];
    const float* bc    = (const float*)d_in[12 + off];
    const float* Wg    = (const float*)d_in[13 + off];
    const float* bg    = (const float*)d_in[14 + off];
    const float* Wx    = (const float*)d_in[15 + off];
    const float* Whh   = (const float*)d_in[16 + off];
    const float* blstm = (const float*)d_in[17 + off];
    const float* Wout  = (const float*)d_in[18 + off];
    const float* bout  = (const float*)d_in[19 + off];
    float* out = (float*)d_out;

    k_mean<<<(Bc * Fc + 255) / 256, 256>>>(feat);
    k_h0c0<<<(2 * Bc * Hc + 255) / 256, 256>>>(Wh, bh, Wc, bc);
    k_encproj<<<dim3(32, 8), 256>>>(feat, W2, b2);
    k_x0<<<(Bc * Ec + 255) / 256, 256>>>(emb);

    for (int t = 0; t < Tc; t++) {
        int rp = t & 1, wp = 1 - rp;
        k_hq_glin<<<28, 256>>>(W1, b1, Wg, bg, rp);
        k_attn<<<Bc, 256>>>(feat, Va, bVa, out, t);
        k_gates<<<dim3(32, 4), 256>>>(Wx, Whh, rp);
        k_lstm<<<(Bc * Hc + 255) / 256, 256>>>(blstm, rp);
        k_logits<<<157, 256>>>(Wout, bout, out, t, wp);
        k_argmax<<<Bc, 256>>>(out, emb, t);
    }
    k_final<<<(2 * Bc * Hc + 255) / 256, 256>>>(out, Tc & 1);
}